// round 15
// baseline (speedup 1.0000x reference)
#include <cuda_runtime.h>
#include <math.h>

#define BH 512
#define BW 512
#define BB 8
#define HW (BH*BW)
#define NTHR 128
#define NW   (NTHR/32)
#define NSTR 1024                  // stream blocks
#define NITER 4                    // iterations per thread (4 px each)
#define GPI  (NSTR*NTHR)           // groups per iteration slab = 131072
#define MAXT 160

// ---- device scratch (static zero-init; kernel self-cleans for graph replay) ----
// per class (stride 5): {S_all, S_out, S_objAdj, cnt_out, cnt_obj}  (log2 domain)
__device__ double g_acc[10];
__device__ unsigned int g_ticket;

__device__ __forceinline__ float ex2f_(float x){ float y; asm("ex2.approx.f32 %0,%1;" : "=f"(y) : "f"(x)); return y; }
__device__ __forceinline__ float lg2f_(float x){ float y; asm("lg2.approx.f32 %0,%1;" : "=f"(y) : "f"(x)); return y; }
__device__ __forceinline__ float rcpf_(float x){ float y; asm("rcp.approx.f32 %0,%1;" : "=f"(y) : "f"(x)); return y; }

__device__ __forceinline__ void decode_target(const float* __restrict__ t,
        int& b, int& cls, float& c, float& s,
        float& X3, float& X4, float& Y3, float& Y4,
        int& ix0, int& ix1, int& iy0, int& iy1) {
    b   = (int)t[0];
    cls = (int)t[1];
    float cx = t[2] * 0.125f, cy = t[3] * 0.125f;
    float ww = t[4] * 0.125f, hh = t[5] * 0.125f;
    c = __cosf(t[6]); s = __sinf(t[6]);
    float x =  cx * c + cy * s;
    float y = -cx * s + cy * c;
    X3 = x - hh * 0.5f; X4 = x + hh * 0.5f;
    Y3 = y - ww * 0.5f; Y4 = y + ww * 0.5f;
    const float X1 = X3 - 0.5f, X2 = X4 + 0.5f;
    const float Y1 = Y3 - 0.5f, Y2 = Y4 + 0.5f;
    float gxmin = 1e30f, gxmax = -1e30f, gymin = 1e30f, gymax = -1e30f;
    #pragma unroll
    for (int k = 0; k < 4; k++) {
        float vx = (k & 1) ? X2 : X1;
        float vy = (k & 2) ? Y2 : Y1;
        float gx = c * vx - s * vy;
        float gy = s * vx + c * vy;
        gxmin = fminf(gxmin, gx); gxmax = fmaxf(gxmax, gx);
        gymin = fminf(gymin, gy); gymax = fmaxf(gymax, gy);
    }
    ix0 = max(0, (int)floorf(gxmin - 0.5f));
    ix1 = min(BW - 1, (int)ceilf(gxmax - 0.5f) + 1);
    iy0 = max(0, (int)floorf(gymin - 0.5f));
    iy1 = min(BH - 1, (int)ceilf(gymax - 0.5f) + 1);
}

// ------------------------------------------------------------------
// Single launch, single wave (1184 = 8x148 CTAs):
// blocks [0,nT) = per-target correction;
// blocks [nT, nT+NSTR) = pipelined stream (4 iters/thread, prefetch depth 2).
// ------------------------------------------------------------------
__global__ __launch_bounds__(NTHR, 8)
void fused_kernel(const float* __restrict__ pred,
                  const float* __restrict__ tgt, int nT,
                  float* __restrict__ out) {
    __shared__ float pc[6][MAXT];
    __shared__ int   nPred;
    __shared__ float sred[NW][4];

    const int tid = threadIdx.x;
    const float LOG2E = 1.4426950408889634f;
    const float LN2   = 0.6931471805599453f;

    if (blockIdx.x >= (unsigned)nT) {
        // ================= STREAM (4 iters, prefetch depth 2) =================
        const int bs  = blockIdx.x - nT;
        const int gid = bs * NTHR + tid;

        float a0 = 0.f, a1 = 0.f;
        float4 b0[3], b1[3];
        // prologue: load iterations 0 and 1 (evict-first: read-once stream)
        #pragma unroll
        for (int pi = 0; pi < 2; pi++) {
            int gp = (gid + pi * GPI) * 4;
            int b  = gp >> 18;
            const float* p = pred + gp + (size_t)b * HW;
            b0[pi] = __ldcs((const float4*)p);
            b1[pi] = __ldcs((const float4*)(p + HW));
        }
        #pragma unroll
        for (int it = 0; it < NITER; it++) {
            if (it + 2 < NITER) {             // prefetch 2 ahead
                int gp2 = (gid + (it + 2) * GPI) * 4;
                int b2  = gp2 >> 18;
                const float* p2 = pred + gp2 + (size_t)b2 * HW;
                b0[(it + 2) % 3] = __ldcs((const float4*)p2);
                b1[(it + 2) % 3] = __ldcs((const float4*)(p2 + HW));
            }
            const float4 A0 = b0[it % 3], A1 = b1[it % 3];
            const int gp = (gid + it * GPI) * 4;

            float xl0[4] = {A0.x * LOG2E, A0.y * LOG2E, A0.z * LOG2E, A0.w * LOG2E};
            float xl1[4] = {A1.x * LOG2E, A1.y * LOG2E, A1.z * LOG2E, A1.w * LOG2E};
            float d0[4], d1[4], tm[4], dm[4];
            #pragma unroll
            for (int k = 0; k < 4; k++) {
                float t0 = ex2f_(xl0[k]);
                float t1 = ex2f_(xl1[k]);
                d0[k] = 1.0f + t0;
                d1[k] = 1.0f + t1;
                tm[k] = fmaxf(t0, t1);
                dm[k] = fmaxf(d0[k], d1[k]);   // = 1 + tm
            }
            a0 += lg2f_((d0[0] * d0[1]) * (d0[2] * d0[3]));
            a1 += lg2f_((d1[0] * d1[1]) * (d1[2] * d1[3]));

            float p01 = dm[0] * dm[1], p23 = dm[2] * dm[3];
            float R   = rcpf_(p01 * p23);
            float r01 = R * p23, r23 = R * p01;
            float* hp = out + 1 + gp;
            __stcs(hp + 0, tm[0] * (r01 * dm[1]));
            __stcs(hp + 1, tm[1] * (r01 * dm[0]));
            __stcs(hp + 2, tm[2] * (r23 * dm[3]));
            __stcs(hp + 3, tm[3] * (r23 * dm[2]));
        }

        #pragma unroll
        for (int off = 16; off; off >>= 1) {
            a0 += __shfl_down_sync(0xffffffffu, a0, off);
            a1 += __shfl_down_sync(0xffffffffu, a1, off);
        }
        const int wid = tid >> 5;
        if ((tid & 31) == 0) { sred[wid][0] = a0; sred[wid][1] = a1; }
        __syncthreads();
        if (tid < 2) {
            float ssum = 0.f;
            #pragma unroll
            for (int wv = 0; wv < NW; wv++) ssum += sred[wv][tid];
            atomicAdd(&g_acc[tid * 5], (double)ssum);   // S_all per class
            __threadfence();
        }
    } else {
        // ================= CORRECTION: target j =================
        const int j = blockIdx.x;
        int b, cls, ix0, ix1, iy0, iy1;
        float c, s, X3, X4, Y3, Y4;
        decode_target(tgt + j * 7, b, cls, c, s, X3, X4, Y3, Y4, ix0, ix1, iy0, iy1);

        if (tid == 0) nPred = 0;
        __syncthreads();

        for (int i = tid; i < j; i += NTHR) {
            int bi, ci_, jx0, jx1, jy0, jy1;
            float cI, sI, A3, A4, B3, B4;
            decode_target(tgt + i * 7, bi, ci_, cI, sI, A3, A4, B3, B4, jx0, jx1, jy0, jy1);
            if (bi != b || ci_ != cls) continue;
            if (jx1 < ix0 || jx0 > ix1 || jy1 < iy0 || jy0 > iy1) continue;
            int p = atomicAdd(&nPred, 1);
            pc[0][p] = cI; pc[1][p] = sI;
            pc[2][p] = A3; pc[3][p] = A4;
            pc[4][p] = B3; pc[5][p] = B4;
        }
        __syncthreads();
        const int np = nPred;

        float s_out = 0.f, s_obj = 0.f, c_out = 0.f, c_obj = 0.f;
        const int Wr = ix1 - ix0 + 1, Hr = iy1 - iy0 + 1;
        if (Wr > 0 && Hr > 0) {
            const float* plane = pred + (size_t)(2 * b + cls) * HW;
            for (int idx = tid; idx < Wr * Hr; idx += NTHR) {
                int ix = ix0 + idx % Wr;
                int iy = iy0 + idx / Wr;
                float gx = ix + 0.5f, gy = iy + 0.5f;
                float vx = fmaf(c, gx, s * gy);
                float vy = fmaf(-s, gx, c * gy);
                bool outer = (vx >= X3 - 0.5f) & (vx <= X4 + 0.5f) &
                             (vy >= Y3 - 0.5f) & (vy <= Y4 + 0.5f);
                if (!outer) continue;
                bool inner = (vx >= X3) & (vx <= X4) & (vy >= Y3) & (vy <= Y4);

                bool prevOut = false, prevIn = false;
                for (int p = 0; p < np; p++) {
                    float cI = pc[0][p], sI = pc[1][p];
                    float A3 = pc[2][p], A4 = pc[3][p];
                    float B3 = pc[4][p], B4 = pc[5][p];
                    float ux = fmaf(cI, gx, sI * gy);
                    float uy = fmaf(-sI, gx, cI * gy);
                    bool oi = (ux >= A3 - 0.5f) & (ux <= A4 + 0.5f) &
                              (uy >= B3 - 0.5f) & (uy <= B4 + 0.5f);
                    bool ii = (ux >= A3) & (ux <= A4) & (uy >= B3) & (uy <= B4);
                    prevOut |= oi; prevIn |= ii;
                }
                bool doOut = !prevOut;
                bool doObj = inner & !prevIn;
                if (doOut | doObj) {
                    float xv = plane[(unsigned)iy * BW + (unsigned)ix];
                    float xl = xv * LOG2E;
                    float L  = lg2f_(1.0f + ex2f_(xl));
                    if (doOut) { s_out += L;      c_out += 1.f; }
                    if (doObj) { s_obj += L - xl; c_obj += 1.f; }
                }
            }
        }
        #pragma unroll
        for (int off = 16; off; off >>= 1) {
            s_out += __shfl_down_sync(0xffffffffu, s_out, off);
            s_obj += __shfl_down_sync(0xffffffffu, s_obj, off);
            c_out += __shfl_down_sync(0xffffffffu, c_out, off);
            c_obj += __shfl_down_sync(0xffffffffu, c_obj, off);
        }
        const int wid = tid >> 5;
        if ((tid & 31) == 0) {
            sred[wid][0] = s_out; sred[wid][1] = s_obj;
            sred[wid][2] = c_out; sred[wid][3] = c_obj;
        }
        __syncthreads();
        if (tid == 0) {
            float v0 = 0.f, v1 = 0.f, v2 = 0.f, v3 = 0.f;
            #pragma unroll
            for (int wv = 0; wv < NW; wv++) {
                v0 += sred[wv][0]; v1 += sred[wv][1];
                v2 += sred[wv][2]; v3 += sred[wv][3];
            }
            int base = cls * 5;
            if (v0 != 0.f) atomicAdd(&g_acc[base + 1], (double)v0);
            if (v1 != 0.f) atomicAdd(&g_acc[base + 2], (double)v1);
            if (v2 != 0.f) atomicAdd(&g_acc[base + 3], (double)v2);
            if (v3 != 0.f) atomicAdd(&g_acc[base + 4], (double)v3);
            __threadfence();
        }
    }
    __syncthreads();

    // ---- last-block election: finalize scalar loss, self-clean ----
    if (tid == 0) {
        unsigned int ticket = atomicAdd(&g_ticket, 1u);
        if (ticket == gridDim.x - 1) {
            __threadfence();
            double a[10];
            #pragma unroll
            for (int k = 0; k < 10; k++) a[k] = *((volatile double*)&g_acc[k]);
            double loss = 0.0;
            #pragma unroll
            for (int cls = 0; cls < 2; cls++) {
                double S_all = a[cls * 5 + 0];
                double S_out = a[cls * 5 + 1];
                double S_obj = a[cls * 5 + 2];
                double cOut  = a[cls * 5 + 3];
                double cObj  = a[cls * 5 + 4];
                double n_no  = (double)BB * HW - cOut;
                if (cObj > 0.0)
                    loss += LN2 * (S_obj / fmax(cObj, 1.0) +
                                   (S_all - S_out) / fmax(n_no, 1.0));
            }
            out[0] = (float)loss;
            #pragma unroll
            for (int k = 0; k < 10; k++) g_acc[k] = 0.0;
            g_ticket = 0u;
            __threadfence();
        }
    }
}

// ------------------------------------------------------------------
extern "C" void kernel_launch(void* const* d_in, const int* in_sizes, int n_in,
                              void* d_out, int out_size) {
    const float* pred = (const float*)d_in[0];
    const float* tgt  = (const float*)d_in[1];
    int nT = in_sizes[1] / 7;
    if (nT > MAXT) nT = MAXT;
    float* out = (float*)d_out;

    fused_kernel<<<nT + NSTR, NTHR>>>(pred, tgt, nT, out);
}

// round 16
// speedup vs baseline: 1.1379x; 1.1379x over previous
#include <cuda_runtime.h>
#include <math.h>

#define BH 512
#define BW 512
#define BB 8
#define HW (BH*BW)
#define NTHR 256
#define NSTR 256                   // stream blocks (32 per batch image)
#define NITER 8                    // iterations per thread (4 px each)
#define SUBPX 8192                 // px per sub-block per plane = NTHR*4*NITER
#define MAXT 160

// ---- device scratch (static zero-init; kernel self-cleans for graph replay) ----
// per class (stride 5): {S_all, S_out, S_objAdj, cnt_out, cnt_obj}  (log2 domain)
__device__ double g_acc[10];
__device__ unsigned int g_ticket;

__device__ __forceinline__ float ex2f_(float x){ float y; asm("ex2.approx.f32 %0,%1;" : "=f"(y) : "f"(x)); return y; }
__device__ __forceinline__ float lg2f_(float x){ float y; asm("lg2.approx.f32 %0,%1;" : "=f"(y) : "f"(x)); return y; }
__device__ __forceinline__ float rcpf_(float x){ float y; asm("rcp.approx.f32 %0,%1;" : "=f"(y) : "f"(x)); return y; }

__device__ __forceinline__ void decode_target(const float* __restrict__ t,
        int& b, int& cls, float& c, float& s,
        float& X3, float& X4, float& Y3, float& Y4,
        int& ix0, int& ix1, int& iy0, int& iy1) {
    b   = (int)t[0];
    cls = (int)t[1];
    float cx = t[2] * 0.125f, cy = t[3] * 0.125f;
    float ww = t[4] * 0.125f, hh = t[5] * 0.125f;
    c = __cosf(t[6]); s = __sinf(t[6]);
    float x =  cx * c + cy * s;
    float y = -cx * s + cy * c;
    X3 = x - hh * 0.5f; X4 = x + hh * 0.5f;
    Y3 = y - ww * 0.5f; Y4 = y + ww * 0.5f;
    const float X1 = X3 - 0.5f, X2 = X4 + 0.5f;
    const float Y1 = Y3 - 0.5f, Y2 = Y4 + 0.5f;
    float gxmin = 1e30f, gxmax = -1e30f, gymin = 1e30f, gymax = -1e30f;
    #pragma unroll
    for (int k = 0; k < 4; k++) {
        float vx = (k & 1) ? X2 : X1;
        float vy = (k & 2) ? Y2 : Y1;
        float gx = c * vx - s * vy;
        float gy = s * vx + c * vy;
        gxmin = fminf(gxmin, gx); gxmax = fmaxf(gxmax, gx);
        gymin = fminf(gymin, gy); gymax = fmaxf(gymax, gy);
    }
    ix0 = max(0, (int)floorf(gxmin - 0.5f));
    ix1 = min(BW - 1, (int)ceilf(gxmax - 0.5f) + 1);
    iy0 = max(0, (int)floorf(gymin - 0.5f));
    iy1 = min(BH - 1, (int)ceilf(gymax - 0.5f) + 1);
}

// ------------------------------------------------------------------
// Single launch: blocks [0,nT) = per-target correction;
// blocks [nT, nT+NSTR) = pipelined stream, one image per block,
// all offsets compile-time immediates (depth-2 prefetch, 8 iters).
// ------------------------------------------------------------------
__global__ __launch_bounds__(NTHR, 4)
void fused_kernel(const float* __restrict__ pred,
                  const float* __restrict__ tgt, int nT,
                  float* __restrict__ out) {
    __shared__ float pc[6][MAXT];
    __shared__ int   nPred;
    __shared__ float sred[8][4];

    const int tid = threadIdx.x;
    const float LOG2E = 1.4426950408889634f;
    const float LN2   = 0.6931471805599453f;

    if (blockIdx.x >= (unsigned)nT) {
        // ================= STREAM =================
        const int bs  = blockIdx.x - nT;
        const int b   = bs >> 5;           // image
        const int sub = bs & 31;           // sub-block within image
        const int off = sub * SUBPX + tid * 4;
        const float* p0 = pred + (size_t)(2 * b) * HW + off;   // plane 0 base
        const float* p1 = p0 + HW;                              // plane 1 base
        float*       hp = out + 1 + (size_t)b * HW + off;       // heatmap base

        float a0 = 0.f, a1 = 0.f;
        float4 b0[3], b1[3];
        // prologue: iterations 0,1 (immediate offsets)
        b0[0] = *(const float4*)(p0);          b1[0] = *(const float4*)(p1);
        b0[1] = *(const float4*)(p0 + 1024);   b1[1] = *(const float4*)(p1 + 1024);
        #pragma unroll
        for (int it = 0; it < NITER; it++) {
            if (it + 2 < NITER) {              // prefetch 2 ahead, imm offset
                b0[(it + 2) % 3] = *(const float4*)(p0 + (it + 2) * 1024);
                b1[(it + 2) % 3] = *(const float4*)(p1 + (it + 2) * 1024);
            }
            const float4 A0 = b0[it % 3], A1 = b1[it % 3];

            float xl0[4] = {A0.x * LOG2E, A0.y * LOG2E, A0.z * LOG2E, A0.w * LOG2E};
            float xl1[4] = {A1.x * LOG2E, A1.y * LOG2E, A1.z * LOG2E, A1.w * LOG2E};
            float d0[4], d1[4], tm[4], dm[4];
            #pragma unroll
            for (int k = 0; k < 4; k++) {
                float t0 = ex2f_(xl0[k]);
                float t1 = ex2f_(xl1[k]);
                d0[k] = 1.0f + t0;
                d1[k] = 1.0f + t1;
                tm[k] = fmaxf(t0, t1);
                dm[k] = fmaxf(d0[k], d1[k]);   // = 1 + max(t0,t1)
            }
            a0 += lg2f_((d0[0] * d0[1]) * (d0[2] * d0[3]));
            a1 += lg2f_((d1[0] * d1[1]) * (d1[2] * d1[3]));

            float p01 = dm[0] * dm[1], p23 = dm[2] * dm[3];
            float R   = rcpf_(p01 * p23);
            float r01 = R * p23, r23 = R * p01;
            hp[it * 1024 + 0] = tm[0] * (r01 * dm[1]);
            hp[it * 1024 + 1] = tm[1] * (r01 * dm[0]);
            hp[it * 1024 + 2] = tm[2] * (r23 * dm[3]);
            hp[it * 1024 + 3] = tm[3] * (r23 * dm[2]);
        }

        #pragma unroll
        for (int off2 = 16; off2; off2 >>= 1) {
            a0 += __shfl_down_sync(0xffffffffu, a0, off2);
            a1 += __shfl_down_sync(0xffffffffu, a1, off2);
        }
        const int wid = tid >> 5;
        if ((tid & 31) == 0) { sred[wid][0] = a0; sred[wid][1] = a1; }
        __syncthreads();
        if (tid < 2) {
            float ssum = 0.f;
            #pragma unroll
            for (int wv = 0; wv < 8; wv++) ssum += sred[wv][tid];
            atomicAdd(&g_acc[tid * 5], (double)ssum);   // S_all per class
            __threadfence();
        }
    } else {
        // ================= CORRECTION: target j =================
        const int j = blockIdx.x;
        int b, cls, ix0, ix1, iy0, iy1;
        float c, s, X3, X4, Y3, Y4;
        decode_target(tgt + j * 7, b, cls, c, s, X3, X4, Y3, Y4, ix0, ix1, iy0, iy1);

        if (tid == 0) nPred = 0;
        __syncthreads();

        for (int i = tid; i < j; i += NTHR) {
            int bi, ci_, jx0, jx1, jy0, jy1;
            float cI, sI, A3, A4, B3, B4;
            decode_target(tgt + i * 7, bi, ci_, cI, sI, A3, A4, B3, B4, jx0, jx1, jy0, jy1);
            if (bi != b || ci_ != cls) continue;
            if (jx1 < ix0 || jx0 > ix1 || jy1 < iy0 || jy0 > iy1) continue;
            int p = atomicAdd(&nPred, 1);
            pc[0][p] = cI; pc[1][p] = sI;
            pc[2][p] = A3; pc[3][p] = A4;
            pc[4][p] = B3; pc[5][p] = B4;
        }
        __syncthreads();
        const int np = nPred;

        float s_out = 0.f, s_obj = 0.f, c_out = 0.f, c_obj = 0.f;
        const int Wr = ix1 - ix0 + 1, Hr = iy1 - iy0 + 1;
        if (Wr > 0 && Hr > 0) {
            const float* plane = pred + (size_t)(2 * b + cls) * HW;
            for (int idx = tid; idx < Wr * Hr; idx += NTHR) {
                int ix = ix0 + idx % Wr;
                int iy = iy0 + idx / Wr;
                float gx = ix + 0.5f, gy = iy + 0.5f;
                float vx = fmaf(c, gx, s * gy);
                float vy = fmaf(-s, gx, c * gy);
                bool outer = (vx >= X3 - 0.5f) & (vx <= X4 + 0.5f) &
                             (vy >= Y3 - 0.5f) & (vy <= Y4 + 0.5f);
                if (!outer) continue;
                bool inner = (vx >= X3) & (vx <= X4) & (vy >= Y3) & (vy <= Y4);

                bool prevOut = false, prevIn = false;
                for (int p = 0; p < np; p++) {
                    float cI = pc[0][p], sI = pc[1][p];
                    float A3 = pc[2][p], A4 = pc[3][p];
                    float B3 = pc[4][p], B4 = pc[5][p];
                    float ux = fmaf(cI, gx, sI * gy);
                    float uy = fmaf(-sI, gx, cI * gy);
                    bool oi = (ux >= A3 - 0.5f) & (ux <= A4 + 0.5f) &
                              (uy >= B3 - 0.5f) & (uy <= B4 + 0.5f);
                    bool ii = (ux >= A3) & (ux <= A4) & (uy >= B3) & (uy <= B4);
                    prevOut |= oi; prevIn |= ii;
                }
                bool doOut = !prevOut;
                bool doObj = inner & !prevIn;
                if (doOut | doObj) {
                    float xv = plane[(unsigned)iy * BW + (unsigned)ix];
                    float xl = xv * LOG2E;
                    float L  = lg2f_(1.0f + ex2f_(xl));
                    if (doOut) { s_out += L;      c_out += 1.f; }
                    if (doObj) { s_obj += L - xl; c_obj += 1.f; }
                }
            }
        }
        #pragma unroll
        for (int off2 = 16; off2; off2 >>= 1) {
            s_out += __shfl_down_sync(0xffffffffu, s_out, off2);
            s_obj += __shfl_down_sync(0xffffffffu, s_obj, off2);
            c_out += __shfl_down_sync(0xffffffffu, c_out, off2);
            c_obj += __shfl_down_sync(0xffffffffu, c_obj, off2);
        }
        const int wid = tid >> 5;
        if ((tid & 31) == 0) {
            sred[wid][0] = s_out; sred[wid][1] = s_obj;
            sred[wid][2] = c_out; sred[wid][3] = c_obj;
        }
        __syncthreads();
        if (tid == 0) {
            float v0 = 0.f, v1 = 0.f, v2 = 0.f, v3 = 0.f;
            #pragma unroll
            for (int wv = 0; wv < 8; wv++) {
                v0 += sred[wv][0]; v1 += sred[wv][1];
                v2 += sred[wv][2]; v3 += sred[wv][3];
            }
            int base = cls * 5;
            if (v0 != 0.f) atomicAdd(&g_acc[base + 1], (double)v0);
            if (v1 != 0.f) atomicAdd(&g_acc[base + 2], (double)v1);
            if (v2 != 0.f) atomicAdd(&g_acc[base + 3], (double)v2);
            if (v3 != 0.f) atomicAdd(&g_acc[base + 4], (double)v3);
            __threadfence();
        }
    }
    __syncthreads();

    // ---- last-block election: finalize scalar loss, self-clean ----
    if (tid == 0) {
        unsigned int ticket = atomicAdd(&g_ticket, 1u);
        if (ticket == gridDim.x - 1) {
            __threadfence();
            double a[10];
            #pragma unroll
            for (int k = 0; k < 10; k++) a[k] = *((volatile double*)&g_acc[k]);
            double loss = 0.0;
            #pragma unroll
            for (int cls = 0; cls < 2; cls++) {
                double S_all = a[cls * 5 + 0];
                double S_out = a[cls * 5 + 1];
                double S_obj = a[cls * 5 + 2];
                double cOut  = a[cls * 5 + 3];
                double cObj  = a[cls * 5 + 4];
                double n_no  = (double)BB * HW - cOut;
                if (cObj > 0.0)
                    loss += LN2 * (S_obj / fmax(cObj, 1.0) +
                                   (S_all - S_out) / fmax(n_no, 1.0));
            }
            out[0] = (float)loss;
            #pragma unroll
            for (int k = 0; k < 10; k++) g_acc[k] = 0.0;
            g_ticket = 0u;
            __threadfence();
        }
    }
}

// ------------------------------------------------------------------
extern "C" void kernel_launch(void* const* d_in, const int* in_sizes, int n_in,
                              void* d_out, int out_size) {
    const float* pred = (const float*)d_in[0];
    const float* tgt  = (const float*)d_in[1];
    int nT = in_sizes[1] / 7;
    if (nT > MAXT) nT = MAXT;
    float* out = (float*)d_out;

    fused_kernel<<<nT + NSTR, NTHR>>>(pred, tgt, nT, out);
}